// round 1
// baseline (speedup 1.0000x reference)
#include <cuda_runtime.h>

// Problem constants
#define NM      31
#define NPLANE  (NM*NM)        // 961
#define NK      (NM*NM*NM)     // 29791
#define NB      8
#define NPTS    3000
#define NCH     4
#define NBW     12
#define NXH     16             // half-space planes nx = 0..15
#define TWO_PI_L 0.628318530717958647692f   // 2*pi/L, L=10
#define HALF_L   5.0f
#define INV2V    (1.0f/2000.0f)             // 1/(2*V), V=1000

// Scratch (static device globals; allocation-free per harness rules)
__device__ float2 g_E[NB*NPTS*3*NM];          // [pidx][dim][n]  17.9 MB
__device__ float2 g_F[NB*NCH*NXH*NPLANE];     // mult-folded structure factor, 3.94 MB
__device__ float  g_mult[NK];
__device__ float  g_diag;

__device__ __forceinline__ float2 cmul(float2 a, float2 b) {
    return make_float2(a.x*b.x - a.y*b.y, a.x*b.y + a.y*b.x);
}

// ---------------------------------------------------------------------------
// 1) mult(k) = sum_b amp_b * exp(-k2 * exp(2*shift_b)), zeroed at k=0
// ---------------------------------------------------------------------------
__global__ void mult_kernel(const float* __restrict__ shift,
                            const float* __restrict__ amp) {
    int i = blockIdx.x * blockDim.x + threadIdx.x;
    if (i >= NK) return;
    int ix = i / NPLANE;
    int r  = i - ix * NPLANE;
    int iy = r / NM;
    int iz = r - iy * NM;
    float kx = TWO_PI_L * (float)(ix - 15);
    float ky = TWO_PI_L * (float)(iy - 15);
    float kz = TWO_PI_L * (float)(iz - 15);
    float k2 = kx*kx + ky*ky + kz*kz;
    float m = 0.0f;
#pragma unroll
    for (int b = 0; b < NBW; b++) {
        m += amp[b] * __expf(-k2 * __expf(2.0f * shift[b]));
    }
    if (k2 == 0.0f) m = 0.0f;
    g_mult[i] = m;
}

// ---------------------------------------------------------------------------
// 2) diag_sum = sum(mult) / (2V)  -- single-block deterministic reduction
// ---------------------------------------------------------------------------
__global__ void diag_kernel() {
    __shared__ float sh[1024];
    int tid = threadIdx.x;
    float s = 0.0f;
    for (int i = tid; i < NK; i += 1024) s += g_mult[i];
    sh[tid] = s;
    __syncthreads();
    for (int o = 512; o > 0; o >>= 1) {
        if (tid < o) sh[tid] += sh[tid + o];
        __syncthreads();
    }
    if (tid == 0) g_diag = sh[0] * INV2V;
}

// ---------------------------------------------------------------------------
// 3) E table: E_d[n] = exp(-i * theta_d * n), n = -15..15 (index n+15),
//    via one sincos per dim + unit-circle recurrence.
// ---------------------------------------------------------------------------
__global__ void etab_kernel(const float* __restrict__ pos) {
    int p = blockIdx.x * blockDim.x + threadIdx.x;
    if (p >= NB * NPTS) return;
#pragma unroll
    for (int d = 0; d < 3; d++) {
        float theta = TWO_PI_L * (pos[p*3 + d] - HALF_L);
        float s, c;
        sincosf(theta, &s, &c);
        float2 e1 = make_float2(c, -s);           // exp(-i theta)
        float2* E = &g_E[(p*3 + d) * NM];
        E[15] = make_float2(1.0f, 0.0f);
        float2 cur = make_float2(1.0f, 0.0f);
#pragma unroll
        for (int m = 1; m <= 15; m++) {
            cur = cmul(cur, e1);
            E[15 + m] = cur;
            E[15 - m] = make_float2(cur.x, -cur.y);
        }
    }
}

// ---------------------------------------------------------------------------
// 4) Scatter: one CTA per (x-plane ixh, batch). CTA owns F[b, :, ixh, :, :]
//    in registers (4 ch x 4 z x complex per thread), streams all particles.
//    Epilogue folds mult(k) into F. No atomics.
// ---------------------------------------------------------------------------
__global__ void __launch_bounds__(256) scatter_kernel(const float* __restrict__ charge) {
    const int ixh = blockIdx.x;          // 0..15
    const int b   = blockIdx.y;
    const int ix  = 15 + ixh;            // nx >= 0
    const int tid = threadIdx.x;
    const int iy  = tid >> 3;            // 0..31 (31 inactive)
    const int zg  = tid & 7;
    const int z0  = zg * 4;
    const bool act = (iy < NM);

    __shared__ float2 sEx[32];
    __shared__ float2 sEy[32][32];
    __shared__ float2 sEz[32][32];
    __shared__ float4 sCh[32];

    float2 acc[NCH][4];
#pragma unroll
    for (int c = 0; c < NCH; c++)
#pragma unroll
        for (int zl = 0; zl < 4; zl++) acc[c][zl] = make_float2(0.0f, 0.0f);

    for (int j0 = 0; j0 < NPTS; j0 += 32) {
        // cooperative load of a 32-particle chunk
        for (int idx = tid; idx < 32*32; idx += 256) {
            int p = idx >> 5, i = idx & 31;
            int j = j0 + p;
            float2 vy = make_float2(0.0f, 0.0f), vz = vy;
            if (i < NM && j < NPTS) {
                int base = (b*NPTS + j) * 3;
                vy = g_E[(base + 1)*NM + i];
                vz = g_E[(base + 2)*NM + i];
            }
            sEy[p][i] = vy;
            sEz[p][i] = vz;
        }
        if (tid < 32) {
            int j = j0 + tid;
            float2 vx = make_float2(0.0f, 0.0f);
            float4 c4 = make_float4(0.0f, 0.0f, 0.0f, 0.0f);
            if (j < NPTS) {
                vx = g_E[((b*NPTS + j)*3 + 0)*NM + ix];
                c4 = *reinterpret_cast<const float4*>(&charge[(b*NPTS + j)*NCH]);
            }
            sEx[tid] = vx;
            sCh[tid] = c4;
        }
        __syncthreads();

        if (act) {
#pragma unroll 4
            for (int p = 0; p < 32; p++) {
                float2 exy = cmul(sEx[p], sEy[p][iy]);
                float4 c4 = sCh[p];
                float2 w0 = make_float2(c4.x*exy.x, c4.x*exy.y);
                float2 w1 = make_float2(c4.y*exy.x, c4.y*exy.y);
                float2 w2 = make_float2(c4.z*exy.x, c4.z*exy.y);
                float2 w3 = make_float2(c4.w*exy.x, c4.w*exy.y);
#pragma unroll
                for (int zl = 0; zl < 4; zl++) {
                    float2 ez = sEz[p][z0 + zl];
                    acc[0][zl].x += w0.x*ez.x - w0.y*ez.y;
                    acc[0][zl].y += w0.x*ez.y + w0.y*ez.x;
                    acc[1][zl].x += w1.x*ez.x - w1.y*ez.y;
                    acc[1][zl].y += w1.x*ez.y + w1.y*ez.x;
                    acc[2][zl].x += w2.x*ez.x - w2.y*ez.y;
                    acc[2][zl].y += w2.x*ez.y + w2.y*ez.x;
                    acc[3][zl].x += w3.x*ez.x - w3.y*ez.y;
                    acc[3][zl].y += w3.x*ez.y + w3.y*ez.x;
                }
            }
        }
        __syncthreads();
    }

    if (act) {
#pragma unroll
        for (int zl = 0; zl < 4; zl++) {
            int z = z0 + zl;
            if (z < NM) {
                float m = g_mult[ix*NPLANE + iy*NM + z];
#pragma unroll
                for (int c = 0; c < NCH; c++) {
                    g_F[((b*NCH + c)*NXH + ixh)*NPLANE + iy*NM + z] =
                        make_float2(acc[c][zl].x * m, acc[c][zl].y * m);
                }
            }
        }
    }
}

// ---------------------------------------------------------------------------
// 5) Gather: one CTA per (batch, 8 particles). F plane staged in smem and
//    reused across the 8 particles; per-thread F tile held in registers.
//    Hermitian weight (1 for nx=0, 2 otherwise) folded into Ex.
//    energy_j = sum_c q_jc * (Re(phi_jc)/(2V) - diag)
// ---------------------------------------------------------------------------
__global__ void __launch_bounds__(256) gather_kernel(const float* __restrict__ charge,
                                                     float* __restrict__ out) {
    const int b   = blockIdx.y;
    const int j0  = blockIdx.x * 8;
    const int tid = threadIdx.x;
    const int iy  = tid >> 3;
    const int zg  = tid & 7;
    const int z0  = zg * 4;
    const bool act = (iy < NM);
    const int warp = tid >> 5;
    const int lane = tid & 31;

    __shared__ float2 sF[NCH*NPLANE];        // one x-plane, 30.75 KB
    __shared__ float2 pExw[8][NXH];          // weight-folded Ex
    __shared__ float2 pEy[8][32];
    __shared__ float2 pEz[8][32];            // slot 31 zeroed
    __shared__ float4 pCh[8];
    __shared__ float  red[8][32];
    __shared__ float  sfin[32];

    // particle data
    for (int idx = tid; idx < 8*32; idx += 256) {
        int p = idx >> 5, i = idx & 31;
        int j = j0 + p;
        int base = (b*NPTS + j) * 3;
        float2 vy = make_float2(0.0f, 0.0f), vz = vy;
        if (i < NM) {
            vy = g_E[(base + 1)*NM + i];
            vz = g_E[(base + 2)*NM + i];
        }
        pEy[p][i] = vy;
        pEz[p][i] = vz;
    }
    if (tid < 8*NXH) {
        int p = tid >> 4, i = tid & 15;
        int j = j0 + p;
        float2 ex = g_E[((b*NPTS + j)*3 + 0)*NM + 15 + i];
        float w = (i == 0) ? 1.0f : 2.0f;    // Hermitian weight
        pExw[p][i] = make_float2(w*ex.x, w*ex.y);
    }
    if (tid < 8) {
        pCh[tid] = *reinterpret_cast<const float4*>(&charge[(b*NPTS + j0 + tid)*NCH]);
    }

    float acc[8][NCH];
#pragma unroll
    for (int p = 0; p < 8; p++)
#pragma unroll
        for (int c = 0; c < NCH; c++) acc[p][c] = 0.0f;

    for (int ixh = 0; ixh < NXH; ixh++) {
        __syncthreads();   // protects sF reuse (and particle loads on iter 0)
        for (int idx = tid; idx < NCH*NPLANE; idx += 256) {
            int c = idx / NPLANE;
            int r = idx - c * NPLANE;
            sF[idx] = g_F[((b*NCH + c)*NXH + ixh)*NPLANE + r];
        }
        __syncthreads();

        if (act) {
            float2 Freg[NCH][4];
#pragma unroll
            for (int c = 0; c < NCH; c++)
#pragma unroll
                for (int zl = 0; zl < 4; zl++) {
                    int z = z0 + zl;
                    Freg[c][zl] = (z < NM) ? sF[c*NPLANE + iy*NM + z]
                                           : make_float2(0.0f, 0.0f);
                }
#pragma unroll
            for (int p = 0; p < 8; p++) {
                float2 exy = cmul(pExw[p][ixh], pEy[p][iy]);
#pragma unroll
                for (int zl = 0; zl < 4; zl++) {
                    float2 e = cmul(exy, pEz[p][z0 + zl]);
                    acc[p][0] += Freg[0][zl].x*e.x + Freg[0][zl].y*e.y;
                    acc[p][1] += Freg[1][zl].x*e.x + Freg[1][zl].y*e.y;
                    acc[p][2] += Freg[2][zl].x*e.x + Freg[2][zl].y*e.y;
                    acc[p][3] += Freg[3][zl].x*e.x + Freg[3][zl].y*e.y;
                }
            }
        }
    }
    __syncthreads();

    // block reduction: 32 values (p,c) per thread -> warp xor-shuffle -> smem
#pragma unroll
    for (int p = 0; p < 8; p++) {
#pragma unroll
        for (int c = 0; c < NCH; c++) {
            float v = acc[p][c];
#pragma unroll
            for (int off = 16; off > 0; off >>= 1)
                v += __shfl_xor_sync(0xffffffffu, v, off);
            if (lane == 0) red[warp][p*NCH + c] = v;
        }
    }
    __syncthreads();
    if (tid < 32) {
        float s = 0.0f;
#pragma unroll
        for (int w = 0; w < 8; w++) s += red[w][tid];
        sfin[tid] = s;
    }
    __syncthreads();
    if (tid < 8) {
        float diag = g_diag;
        float4 c4 = pCh[tid];
        float e = c4.x * (sfin[tid*NCH + 0]*INV2V - diag)
                + c4.y * (sfin[tid*NCH + 1]*INV2V - diag)
                + c4.z * (sfin[tid*NCH + 2]*INV2V - diag)
                + c4.w * (sfin[tid*NCH + 3]*INV2V - diag);
        out[b*NPTS + j0 + tid] = e;
    }
}

// ---------------------------------------------------------------------------
// Launch. Inputs (metadata order): pos f32[8,3000,3], charge f32[8,3000,4],
// shift f32[12], amplitud f32[12]. Output: f32[8,3000].
// ---------------------------------------------------------------------------
extern "C" void kernel_launch(void* const* d_in, const int* in_sizes, int n_in,
                              void* d_out, int out_size) {
    const float* pos    = (const float*)d_in[0];
    const float* charge = (const float*)d_in[1];
    const float* shift  = (const float*)d_in[2];
    const float* amp    = (const float*)d_in[3];
    float* out = (float*)d_out;

    mult_kernel<<<(NK + 255)/256, 256>>>(shift, amp);
    diag_kernel<<<1, 1024>>>();
    etab_kernel<<<(NB*NPTS + 127)/128, 128>>>(pos);
    scatter_kernel<<<dim3(NXH, NB), 256>>>(charge);
    gather_kernel<<<dim3(NPTS/8, NB), 256>>>(charge, out);
}